// round 6
// baseline (speedup 1.0000x reference)
#include <cuda_runtime.h>
#include <cuda_bf16.h>
#include <cstdint>

#define C_CLASSES 6625
#define D_DIM     96
#define WPB       8            // warps per block
#define NTHREADS  (WPB * 32)
#define EPSV      1e-7f
#define INFV      1e11f

// clip() applied to the masked-out zeros contributes (C-1)*EPS exactly.
__global__ void cl_init_out(float* out) {
    out[0] = (float)(C_CLASSES - 1) * EPSV;
}

__device__ __forceinline__ void cmp4(float4 q, int base, float& best, int& bidx) {
    if (q.x > best) { best = q.x; bidx = base;     }
    if (q.y > best) { best = q.y; bidx = base + 1; }
    if (q.z > best) { best = q.z; bidx = base + 2; }
    if (q.w > best) { best = q.w; bidx = base + 3; }
}

__global__ __launch_bounds__(NTHREADS, 8)
void center_loss_kernel(const float* __restrict__ features,  // [N, 96]
                        const float* __restrict__ predicts,  // [N, 6625]
                        const float* __restrict__ centers,   // [6625, 96]
                        float* __restrict__ out,
                        int N)
{
    const int warp = threadIdx.x >> 5;
    const int lane = threadIdx.x & 31;
    const int n    = blockIdx.x * WPB + warp;
    if (n >= N) return;

    const float* row = predicts + (size_t)n * C_CLASSES;

    // Row stride 6625 floats = 26500 B is only 4B-aligned -> per-row scalar
    // prologue so the vector body can use LDG.128 safely.
    const int mis = ((int)((uintptr_t)row >> 2)) & 3;
    const int p   = (4 - mis) & 3;                 // scalar prologue count
    const int nv  = (C_CLASSES - p) >> 2;          // float4 count (1655/1656)
    const int tail_start = p + (nv << 2);

    const float4* vrow = (const float4*)(row + p);

    float best = -3.402823466e38f;
    int   bidx = C_CLASSES;

    // Main loop: uniform trip count across the warp (nv is warp-uniform).
    // 4 independent LDG.128 per iteration -> MLP 4, perfectly coalesced.
    int b = 0;
    for (; b + 128 <= nv; b += 128) {
        const int v = b + lane;
        float4 q0 = __ldg(vrow + v);
        float4 q1 = __ldg(vrow + v + 32);
        float4 q2 = __ldg(vrow + v + 64);
        float4 q3 = __ldg(vrow + v + 96);
        cmp4(q0, p + (v << 2),         best, bidx);
        cmp4(q1, p + ((v + 32) << 2),  best, bidx);
        cmp4(q2, p + ((v + 64) << 2),  best, bidx);
        cmp4(q3, p + ((v + 96) << 2),  best, bidx);
    }
    // Remainder float4s (< 4 per lane).
    for (int v = b + lane; v < nv; v += 32) {
        float4 q = __ldg(vrow + v);
        cmp4(q, p + (v << 2), best, bidx);
    }
    // Scalar prologue (indices below all vector indices: needs tie-break).
    if (lane < p) {
        float v = __ldg(row + lane);
        if (v > best || (v == best && lane < bidx)) { best = v; bidx = lane; }
    }
    // Scalar tail (indices above all vector indices: strict > suffices).
    {
        int t = tail_start + lane;
        if (t < C_CLASSES) {
            float v = __ldg(row + t);
            if (v > best) { best = v; bidx = t; }
        }
    }

    // Warp (val, idx) reduce, min-idx tie-break (jnp.argmax first occurrence).
    #pragma unroll
    for (int off = 16; off > 0; off >>= 1) {
        float ov = __shfl_down_sync(0xffffffffu, best, off);
        int   oi = __shfl_down_sync(0xffffffffu, bidx, off);
        if (ov > best || (ov == best && oi < bidx)) { best = ov; bidx = oi; }
    }
    const int label = __shfl_sync(0xffffffffu, bidx, 0);

    // Squared distance over D=96: 24 lanes x float4 (rows are 16B-aligned).
    float part = 0.0f;
    if (lane < D_DIM / 4) {
        float4 f = __ldg((const float4*)(features + (size_t)n * D_DIM) + lane);
        float4 c = __ldg((const float4*)(centers + (size_t)label * D_DIM) + lane);
        float dx = f.x - c.x, dy = f.y - c.y, dz = f.z - c.z, dw = f.w - c.w;
        part = dx * dx + dy * dy + dz * dz + dw * dw;
    }
    #pragma unroll
    for (int off = 16; off > 0; off >>= 1)
        part += __shfl_down_sync(0xffffffffu, part, off);

    if (lane == 0) {
        float dist = fminf(fmaxf(part, EPSV), INFV);
        atomicAdd(out, dist / (float)N);
    }
}

extern "C" void kernel_launch(void* const* d_in, const int* in_sizes, int n_in,
                              void* d_out, int out_size) {
    const float* features = (const float*)d_in[0];  // [B,T,D] fp32
    const float* predicts = (const float*)d_in[1];  // [B,T,C] fp32
    const float* centers  = (const float*)d_in[2];  // [C,D]   fp32
    float* out = (float*)d_out;

    const int N = in_sizes[0] / D_DIM;  // B*T = 8192

    cl_init_out<<<1, 1>>>(out);
    const int nblocks = (N + WPB - 1) / WPB;  // 1024 -> single wave
    center_loss_kernel<<<nblocks, NTHREADS>>>(features, predicts, centers, out, N);
}

// round 8
// speedup vs baseline: 1.1335x; 1.1335x over previous
#include <cuda_runtime.h>
#include <cuda_bf16.h>
#include <cstdint>

#define C_CLASSES 6625
#define D_DIM     96
#define NTHREADS  256
#define NWARPS    (NTHREADS / 32)
#define EPSV      1e-7f
#define INFV      1e11f

// clip() applied to the masked-out zeros contributes (C-1)*EPS exactly.
__global__ void cl_init_out(float* out) {
    out[0] = (float)(C_CLASSES - 1) * EPSV;
}

// Tournament compare: independent fmax tree, single dependent compare vs best,
// index recovered only on the (rare) update. First occurrence within the quad
// is preserved by testing x,y,z,w in order.
__device__ __forceinline__ void cmp4t(float4 q, int base, float& best, int& bidx) {
    float m = fmaxf(fmaxf(q.x, q.y), fmaxf(q.z, q.w));
    if (m > best) {
        best = m;
        bidx = (q.x == m) ? base
             : (q.y == m) ? base + 1
             : (q.z == m) ? base + 2
             :              base + 3;
    }
}

__global__ __launch_bounds__(NTHREADS, 8)
void center_loss_kernel(const float* __restrict__ features,  // [N, 96]
                        const float* __restrict__ predicts,  // [N, 6625]
                        const float* __restrict__ centers,   // [6625, 96]
                        float* __restrict__ out,
                        int N)
{
    const int n   = blockIdx.x;
    const int tid = threadIdx.x;
    const float* row = predicts + (size_t)n * C_CLASSES;

    // Row stride 6625 floats = 26500 B is only 4B-aligned -> per-row scalar
    // prologue so the vector body can use LDG.128 safely.
    const int mis = ((int)((uintptr_t)row >> 2)) & 3;
    const int p   = (4 - mis) & 3;                      // scalar prologue count
    const int nv  = (C_CLASSES - p) >> 2;               // float4 count (>= 1655)
    const int tail_start = p + (nv << 2);

    const float4* vrow = (const float4*)(row + p);

    float best = -3.402823466e38f;
    int   bidx = C_CLASSES;

    // Software-pipelined scan: <=4 float4s live at a time (regs <= 32),
    // MLP ~4.  Indices tid + i*256 for i<6 are always < nv (1535 < 1655).
    float4 a0 = __ldg(vrow + tid);
    float4 a1 = __ldg(vrow + tid + 1 * NTHREADS);
    float4 a2 = __ldg(vrow + tid + 2 * NTHREADS);
    float4 a3 = __ldg(vrow + tid + 3 * NTHREADS);

    cmp4t(a0, p + (tid << 2),                    best, bidx);
    float4 b0 = __ldg(vrow + tid + 4 * NTHREADS);
    cmp4t(a1, p + ((tid + 1 * NTHREADS) << 2),   best, bidx);
    float4 b1 = __ldg(vrow + tid + 5 * NTHREADS);
    cmp4t(a2, p + ((tid + 2 * NTHREADS) << 2),   best, bidx);
    const int v6 = tid + 6 * NTHREADS;
    float4 b2 = (v6 < nv) ? __ldg(vrow + v6)
                          : make_float4(-3.4e38f, -3.4e38f, -3.4e38f, -3.4e38f);
    cmp4t(a3, p + ((tid + 3 * NTHREADS) << 2),   best, bidx);
    cmp4t(b0, p + ((tid + 4 * NTHREADS) << 2),   best, bidx);
    cmp4t(b1, p + ((tid + 5 * NTHREADS) << 2),   best, bidx);
    if (v6 < nv) cmp4t(b2, p + (v6 << 2),        best, bidx);

    // Scalar prologue (indices below all vector indices: needs tie-break).
    if (tid < p) {
        float v = __ldg(row + tid);
        if (v > best || (v == best && tid < bidx)) { best = v; bidx = tid; }
    }
    // Scalar tail (indices above all vector indices: strict > suffices).
    {
        int t = tail_start + tid;
        if (t < C_CLASSES) {
            float v = __ldg(row + t);
            if (v > best) { best = v; bidx = t; }
        }
    }

    // Warp (val, idx) reduce, min-idx tie-break (jnp.argmax first occurrence).
    #pragma unroll
    for (int off = 16; off > 0; off >>= 1) {
        float ov = __shfl_down_sync(0xffffffffu, best, off);
        int   oi = __shfl_down_sync(0xffffffffu, bidx, off);
        if (ov > best || (ov == best && oi < bidx)) { best = ov; bidx = oi; }
    }

    __shared__ float swv[NWARPS];
    __shared__ int   swi[NWARPS];
    __shared__ int   slabel;
    if ((tid & 31) == 0) { swv[tid >> 5] = best; swi[tid >> 5] = bidx; }
    __syncthreads();
    if (tid == 0) {
        float bv = swv[0]; int bi = swi[0];
        #pragma unroll
        for (int w = 1; w < NWARPS; w++) {
            if (swv[w] > bv || (swv[w] == bv && swi[w] < bi)) { bv = swv[w]; bi = swi[w]; }
        }
        slabel = bi;
    }
    __syncthreads();

    // Squared distance over D=96: warp 0 only, 24 lanes x float4, shfl reduce.
    if (tid < 32) {
        const int label = slabel;
        float part = 0.0f;
        if (tid < D_DIM / 4) {
            float4 f = __ldg((const float4*)(features + (size_t)n * D_DIM) + tid);
            float4 c = __ldg((const float4*)(centers + (size_t)label * D_DIM) + tid);
            float dx = f.x - c.x, dy = f.y - c.y, dz = f.z - c.z, dw = f.w - c.w;
            part = dx * dx + dy * dy + dz * dz + dw * dw;
        }
        #pragma unroll
        for (int off = 16; off > 0; off >>= 1)
            part += __shfl_down_sync(0xffffffffu, part, off);
        if (tid == 0) {
            float dist = fminf(fmaxf(part, EPSV), INFV);
            atomicAdd(out, dist / (float)N);
        }
    }
}

extern "C" void kernel_launch(void* const* d_in, const int* in_sizes, int n_in,
                              void* d_out, int out_size) {
    const float* features = (const float*)d_in[0];  // [B,T,D] fp32
    const float* predicts = (const float*)d_in[1];  // [B,T,C] fp32
    const float* centers  = (const float*)d_in[2];  // [C,D]   fp32
    float* out = (float*)d_out;

    const int N = in_sizes[0] / D_DIM;  // B*T = 8192

    cl_init_out<<<1, 1>>>(out);
    center_loss_kernel<<<N, NTHREADS>>>(features, predicts, centers, out, N);
}